// round 3
// baseline (speedup 1.0000x reference)
#include <cuda_runtime.h>
#include <math.h>

// Problem constants (fixed by the dataset)
#define BB 8
#define NPB 1048576          // elements per batch row
#define ZDIM 1024
#define HID 16
#define NPAIR (HID / 2)
#define CTAS_PER_B 64
#define NBLOCKS (CTAS_PER_B * BB)            // 512
#define TPB 256
#define ELEMS_PER_CTA (NPB / CTAS_PER_B)     // 16384
#define VEC 4
#define ITERS (ELEMS_PER_CTA / (TPB * VEC))  // 16

// fixed-point packing: val = round(out * 2^21) + (1<<44) + (512<<21)
//   bits [0,44): biased sum field, bits [44,64): count
#define SUM_SCALE_F 2097152.0f               // 2^21
#define PACK_BIAS   ((1ULL << 44) + (1ULL << 30))
#define MASK44      ((1ULL << 44) - 1ULL)

typedef unsigned long long ull;

// ---------- packed f32x2 helpers ----------
__device__ __forceinline__ ull pk2(float lo, float hi) {
    ull r;
    asm("mov.b64 %0, {%1, %2};" : "=l"(r) : "r"(__float_as_uint(lo)), "r"(__float_as_uint(hi)));
    return r;
}
__device__ __forceinline__ void upk2(ull p, float& lo, float& hi) {
    unsigned int a, b;
    asm("mov.b64 {%0, %1}, %2;" : "=r"(a), "=r"(b) : "l"(p));
    lo = __uint_as_float(a); hi = __uint_as_float(b);
}
__device__ __forceinline__ ull fma2_(ull a, ull b, ull c) {
    ull d; asm("fma.rn.f32x2 %0, %1, %2, %3;" : "=l"(d) : "l"(a), "l"(b), "l"(c)); return d;
}
__device__ __forceinline__ ull mul2_(ull a, ull b) {
    ull d; asm("mul.rn.f32x2 %0, %1, %2;" : "=l"(d) : "l"(a), "l"(b)); return d;
}
__device__ __forceinline__ ull add2_(ull a, ull b) {
    ull d; asm("add.rn.f32x2 %0, %1, %2;" : "=l"(d) : "l"(a), "l"(b)); return d;
}
__device__ __forceinline__ float rcp_(float x) {
    float r; asm("rcp.approx.ftz.f32 %0, %1;" : "=f"(r) : "f"(x)); return r;
}
__device__ __forceinline__ float rsq_(float x) {
    float r; asm("rsqrt.approx.ftz.f32 %0, %1;" : "=f"(r) : "f"(x)); return r;
}

// Global scratch (zero-initialized at module load; each launch resets it after use).
__device__ ull          g_acc[BB * ZDIM];
__device__ unsigned int g_done;

__global__ __launch_bounds__(TPB, 2) void fik_main_kernel(
    const float* __restrict__ X,   // (B, N)
    const float* __restrict__ Y,   // (B, N, 1)
    const float* __restrict__ Zb,  // (Z,)
    const float* __restrict__ W1,  // (3, HID) row-major
    const float* __restrict__ B1,  // (HID,)
    const float* __restrict__ G,   // gamma (HID,)
    const float* __restrict__ Be,  // beta (HID,)
    const float* __restrict__ W2,  // (HID, 1)
    const float* __restrict__ B2,  // (1,)
    float* __restrict__ OUT)       // (B, 1, Z) == flat B*Z
{
    __shared__ __align__(8) float s_z[ZDIM];
    __shared__ __align__(8) float s_w1[3][HID];
    __shared__ __align__(8) float s_b1[HID], s_g[HID], s_be[HID], s_w2[HID];
    __shared__ float s_b2;
    __shared__ unsigned int s_ticket;

    const int tid = threadIdx.x;

    for (int i = tid; i < ZDIM; i += TPB) s_z[i] = Zb[i];
    if (tid < 3 * HID) s_w1[tid / HID][tid % HID] = W1[tid];
    if (tid < HID) {
        s_b1[tid] = B1[tid];
        s_g[tid]  = G[tid];
        s_be[tid] = Be[tid];
        s_w2[tid] = W2[tid];
    }
    if (tid == 0) s_b2 = B2[0];
    __syncthreads();

    // pair-packed views of the weights (broadcast LDS.64)
    const ull* w10 = (const ull*)s_w1[0];
    const ull* w11 = (const ull*)s_w1[1];
    const ull* w12 = (const ull*)s_w1[2];
    const ull* b1p = (const ull*)s_b1;
    const ull* gp  = (const ull*)s_g;
    const ull* bep = (const ull*)s_be;
    const ull* w2p = (const ull*)s_w2;

    const int b = blockIdx.y;
    const long base = (long)b * NPB + (long)blockIdx.x * ELEMS_PER_CTA;
    const float4* X4 = (const float4*)(X + base);
    const float4* Y4 = (const float4*)(Y + base);
    ull* __restrict__ acc_b = g_acc + b * ZDIM;

    const float z0  = s_z[0];
    const float dz  = s_z[1] - s_z[0];
    const float dzh = dz * 0.5f;
    const float inv_dz = 1.0f / dz;
    const float b2s = s_b2;

    // Eigen/XLA rational erf coefficients, packed (both halves equal)
    const ull A13 = pk2(-2.72614225801306e-10f, -2.72614225801306e-10f);
    const ull A11 = pk2( 2.77068142495902e-08f,  2.77068142495902e-08f);
    const ull A9  = pk2(-2.10102402082508e-06f, -2.10102402082508e-06f);
    const ull A7  = pk2(-5.69250639462346e-05f, -5.69250639462346e-05f);
    const ull A5  = pk2(-7.34990630326855e-04f, -7.34990630326855e-04f);
    const ull A3  = pk2(-2.95459980854025e-03f, -2.95459980854025e-03f);
    const ull A1  = pk2(-1.60960333262415e-02f, -1.60960333262415e-02f);
    const ull Bq8 = pk2(-1.45660718464996e-05f, -1.45660718464996e-05f);
    const ull Bq6 = pk2(-2.13374055278905e-04f, -2.13374055278905e-04f);
    const ull Bq4 = pk2(-1.68282697438203e-03f, -1.68282697438203e-03f);
    const ull Bq2 = pk2(-7.37332916720468e-03f, -7.37332916720468e-03f);
    const ull Bq0 = pk2(-1.42647390514189e-02f, -1.42647390514189e-02f);
    const ull CIS2  = pk2(0.7071067811865476f, 0.7071067811865476f);
    const ull CHALF = pk2(0.5f, 0.5f);

    #pragma unroll 1
    for (int it = 0; it < ITERS; it++) {
        const int vidx = it * TPB + tid;
        const float4 xv4 = X4[vidx];
        const float4 yv4 = Y4[vidx];

        #pragma unroll
        for (int e = 0; e < VEC; e++) {
            const float xv = (e == 0) ? xv4.x : (e == 1) ? xv4.y : (e == 2) ? xv4.z : xv4.w;
            const float yv = (e == 0) ? yv4.x : (e == 1) ? yv4.y : (e == 2) ? yv4.z : yv4.w;

            // bucket index: ceil((x - z0 - dz/2) / dz)
            float t = ((xv - z0) - dzh) * inv_dz;
            int idx = (int)ceilf(t);
            idx = min(max(idx, 0), ZDIM - 1);
            const float zg = s_z[idx];

            const ull x2 = pk2(xv, xv);
            const ull z2 = pk2(zg, zg);
            const ull y2 = pk2(yv, yv);

            // h = [x, zg, y] @ W1 + b1  (8 packed pairs)
            ull h[NPAIR];
            #pragma unroll
            for (int p = 0; p < NPAIR; p++) {
                h[p] = fma2_(x2, w10[p], fma2_(z2, w11[p], fma2_(y2, w12[p], b1p[p])));
            }

            // mean
            ull sa = add2_(add2_(h[0], h[1]), add2_(h[2], h[3]));
            ull sb = add2_(add2_(h[4], h[5]), add2_(h[6], h[7]));
            ull sp = add2_(sa, sb);
            float slo, shi; upk2(sp, slo, shi);
            const float mu = (slo + shi) * (1.0f / HID);
            const ull nmu = pk2(-mu, -mu);

            // deviations + variance
            ull vacc;
            #pragma unroll
            for (int p = 0; p < NPAIR; p++) {
                ull d = add2_(h[p], nmu);
                h[p] = d;                      // h[] now holds deviations
                vacc = (p == 0) ? mul2_(d, d) : fma2_(d, d, vacc);
            }
            float vlo, vhi; upk2(vacc, vlo, vhi);
            const float var = (vlo + vhi) * (1.0f / HID);
            const float rs = rsq_(var + 1e-5f);
            const ull rs2 = pk2(rs, rs);

            // LN affine -> rational-erf gelu -> dot W2
            ull acc = 0ULL;
            #pragma unroll
            for (int p = 0; p < NPAIR; p++) {
                const ull hn = fma2_(mul2_(h[p], rs2), gp[p], bep[p]);
                const ull arg = mul2_(hn, CIS2);
                const ull s = mul2_(arg, arg);
                ull pn = fma2_(s, A13, A11);
                pn = fma2_(s, pn, A9);
                pn = fma2_(s, pn, A7);
                pn = fma2_(s, pn, A5);
                pn = fma2_(s, pn, A3);
                pn = fma2_(s, pn, A1);
                pn = mul2_(pn, arg);           // arg * P(arg^2)
                ull q = fma2_(s, Bq8, Bq6);
                q = fma2_(s, q, Bq4);
                q = fma2_(s, q, Bq2);
                q = fma2_(s, q, Bq0);          // Q < 0 for all s >= 0
                float q0, q1; upk2(q, q0, q1);
                const ull rq = pk2(rcp_(q0), rcp_(q1));
                const ull erf2 = mul2_(pn, rq);
                const ull th = mul2_(hn, CHALF);
                const ull ge = fma2_(th, erf2, th);   // 0.5*hn*(1+erf)
                acc = fma2_(ge, w2p[p], acc);
            }
            float alo, ahi; upk2(acc, alo, ahi);
            const float out = (alo + ahi + b2s) * yv;

            // packed (count | biased fixed-point sum) -> single no-return L2 RED
            const ull pkd = (ull)(__float2ll_rn(out * SUM_SCALE_F) + (long long)PACK_BIAS);
            atomicAdd(&acc_b[idx], pkd);
        }
    }

    // ---- last-CTA finalize: unpack means, write output, reset scratch ----
    __threadfence();
    if (tid == 0) s_ticket = atomicAdd(&g_done, 1u);
    __syncthreads();
    if (s_ticket == NBLOCKS - 1) {
        __threadfence();
        for (int i = tid; i < BB * ZDIM; i += TPB) {
            const ull v = g_acc[i];
            const double cnt = (double)(unsigned int)(v >> 44);
            const double low = (double)(v & MASK44);
            const double sum = low * (1.0 / (double)SUM_SCALE_F) - 512.0 * cnt;
            OUT[i] = (float)(sum / ((cnt > 0.0) ? cnt : 1.0));
            g_acc[i] = 0ULL;
        }
        __syncthreads();
        if (tid == 0) g_done = 0u;
    }
}

extern "C" void kernel_launch(void* const* d_in, const int* in_sizes, int n_in,
                              void* d_out, int out_size) {
    const float* X  = (const float*)d_in[0];
    const float* Y  = (const float*)d_in[1];
    const float* Zb = (const float*)d_in[2];
    const float* W1 = (const float*)d_in[3];
    const float* B1 = (const float*)d_in[4];
    const float* G  = (const float*)d_in[5];
    const float* Be = (const float*)d_in[6];
    const float* W2 = (const float*)d_in[7];
    const float* B2 = (const float*)d_in[8];
    float* out = (float*)d_out;

    dim3 grid(CTAS_PER_B, BB);
    fik_main_kernel<<<grid, TPB>>>(X, Y, Zb, W1, B1, G, Be, W2, B2, out);
}

// round 4
// speedup vs baseline: 1.3125x; 1.3125x over previous
#include <cuda_runtime.h>
#include <math.h>

// Problem constants (fixed by the dataset)
#define BB 8
#define NPB 1048576          // elements per batch row
#define ZDIM 1024
#define HID 16
#define NPAIR (HID / 2)
#define CTAS_PER_B 64
#define NBLOCKS (CTAS_PER_B * BB)            // 512
#define TPB 256
#define ELEMS_PER_CTA (NPB / CTAS_PER_B)     // 16384
#define VEC 4
#define ITERS (ELEMS_PER_CTA / (TPB * VEC))  // 16

// fixed-point packing (per-CTA shared accumulator):
//   addend = (1<<46) + (1<<28) + round(out * 2^21),  |out| < 128 so addend > 0
//   bits [0,46): biased sum in 2^-21 units, bits [46,64): count (<= 16384)
#define SUM_SCALE_F 2097152.0f               // 2^21
#define INV_SCALE   (1.0 / 2097152.0)
#define CNT_SHIFT   46
#define ADD_BIAS    ((1ULL << CNT_SHIFT) | (1ULL << 28))
#define MASK46      ((1ULL << CNT_SHIFT) - 1ULL)

typedef unsigned long long ull;

// ---------- packed f32x2 helpers ----------
__device__ __forceinline__ ull pk2(float lo, float hi) {
    ull r;
    asm("mov.b64 %0, {%1, %2};" : "=l"(r) : "r"(__float_as_uint(lo)), "r"(__float_as_uint(hi)));
    return r;
}
__device__ __forceinline__ void upk2(ull p, float& lo, float& hi) {
    unsigned int a, b;
    asm("mov.b64 {%0, %1}, %2;" : "=r"(a), "=r"(b) : "l"(p));
    lo = __uint_as_float(a); hi = __uint_as_float(b);
}
__device__ __forceinline__ ull fma2_(ull a, ull b, ull c) {
    ull d; asm("fma.rn.f32x2 %0, %1, %2, %3;" : "=l"(d) : "l"(a), "l"(b), "l"(c)); return d;
}
__device__ __forceinline__ ull mul2_(ull a, ull b) {
    ull d; asm("mul.rn.f32x2 %0, %1, %2;" : "=l"(d) : "l"(a), "l"(b)); return d;
}
__device__ __forceinline__ ull add2_(ull a, ull b) {
    ull d; asm("add.rn.f32x2 %0, %1, %2;" : "=l"(d) : "l"(a), "l"(b)); return d;
}
__device__ __forceinline__ float rcp_(float x) {
    float r; asm("rcp.approx.ftz.f32 %0, %1;" : "=f"(r) : "f"(x)); return r;
}
__device__ __forceinline__ float rsq_(float x) {
    float r; asm("rsqrt.approx.ftz.f32 %0, %1;" : "=f"(r) : "f"(x)); return r;
}

// Global scratch (zero at module load; last CTA re-zeros for graph replays).
__device__ ull          g_sum_fx[BB * ZDIM];   // signed sum in 2^-21 units (wraps ok)
__device__ unsigned int g_cnt[BB * ZDIM];
__device__ unsigned int g_done;

__global__ __launch_bounds__(TPB, 3) void fik_main_kernel(
    const float* __restrict__ X,   // (B, N)
    const float* __restrict__ Y,   // (B, N, 1)
    const float* __restrict__ Zb,  // (Z,)
    const float* __restrict__ W1,  // (3, HID) row-major
    const float* __restrict__ B1,  // (HID,)
    const float* __restrict__ G,   // gamma (HID,)
    const float* __restrict__ Be,  // beta (HID,)
    const float* __restrict__ W2,  // (HID, 1)
    const float* __restrict__ B2,  // (1,)
    float* __restrict__ OUT)       // (B, 1, Z) == flat B*Z
{
    __shared__ __align__(8) float s_z[ZDIM];
    __shared__ __align__(16) ull s_acc[ZDIM];
    __shared__ __align__(8) float s_w1[3][HID];
    __shared__ __align__(8) float s_b1[HID], s_g[HID], s_be[HID], s_w2h[HID];
    __shared__ float s_b2;
    __shared__ unsigned int s_ticket;

    const int tid = threadIdx.x;

    for (int i = tid; i < ZDIM; i += TPB) {
        s_z[i] = Zb[i];
        s_acc[i] = 0ULL;
    }
    if (tid < 3 * HID) s_w1[tid / HID][tid % HID] = W1[tid];
    if (tid < HID) {
        s_b1[tid]  = B1[tid];
        s_g[tid]   = G[tid];
        s_be[tid]  = Be[tid];
        s_w2h[tid] = W2[tid] * 0.5f;   // fold gelu's 0.5 into W2
    }
    if (tid == 0) s_b2 = B2[0];
    __syncthreads();

    // pair-packed views of the weights (broadcast LDS.64)
    const ull* w10 = (const ull*)s_w1[0];
    const ull* w11 = (const ull*)s_w1[1];
    const ull* w12 = (const ull*)s_w1[2];
    const ull* b1p = (const ull*)s_b1;
    const ull* gp  = (const ull*)s_g;
    const ull* bep = (const ull*)s_be;
    const ull* w2p = (const ull*)s_w2h;

    const int b = blockIdx.y;
    const long base = (long)b * NPB + (long)blockIdx.x * ELEMS_PER_CTA;
    const float4* X4 = (const float4*)(X + base);
    const float4* Y4 = (const float4*)(Y + base);

    const float z0  = s_z[0];
    const float dz  = s_z[1] - s_z[0];
    const float dzh = dz * 0.5f;
    const float inv_dz = 1.0f / dz;
    const float b2s = s_b2;

    // erf(hn/sqrt2) = hn * P'(hn^2) / Q'(hn^2); 1/sqrt2 folded into coeffs.
    const ull A13 = pk2(-3.01199e-12f, -3.01199e-12f);
    const ull A11 = pk2( 6.12251e-10f,  6.12251e-10f);
    const ull A9  = pk2(-9.28533e-08f, -9.28533e-08f);
    const ull A7  = pk2(-5.03151e-06f, -5.03151e-06f);
    const ull A5  = pk2(-1.299293e-04f, -1.299293e-04f);
    const ull A3  = pk2(-1.044617e-03f, -1.044617e-03f);
    const ull A1  = pk2(-1.1381612e-02f, -1.1381612e-02f);
    const ull Bq8 = pk2(-9.10379490e-07f, -9.10379490e-07f);
    const ull Bq6 = pk2(-2.66717569e-05f, -2.66717569e-05f);
    const ull Bq4 = pk2(-4.20706744e-04f, -4.20706744e-04f);
    const ull Bq2 = pk2(-3.68666458e-03f, -3.68666458e-03f);
    const ull Bq0 = pk2(-1.42647391e-02f, -1.42647391e-02f);

    #pragma unroll 1
    for (int it = 0; it < ITERS; it++) {
        const int vidx = it * TPB + tid;
        const float4 xv4 = X4[vidx];
        const float4 yv4 = Y4[vidx];

        #pragma unroll
        for (int e = 0; e < VEC; e++) {
            const float xv = (e == 0) ? xv4.x : (e == 1) ? xv4.y : (e == 2) ? xv4.z : xv4.w;
            const float yv = (e == 0) ? yv4.x : (e == 1) ? yv4.y : (e == 2) ? yv4.z : yv4.w;

            // bucket index: ceil((x - z0 - dz/2) / dz)
            float t = ((xv - z0) - dzh) * inv_dz;
            int idx = (int)ceilf(t);
            idx = min(max(idx, 0), ZDIM - 1);
            const float zg = s_z[idx];

            const ull x2 = pk2(xv, xv);
            const ull z2 = pk2(zg, zg);
            const ull y2 = pk2(yv, yv);

            // h = [x, zg, y] @ W1 + b1; accumulate sum(h) and sum(h^2) together
            ull h[NPAIR];
            ull sum2, sq2;
            #pragma unroll
            for (int p = 0; p < NPAIR; p++) {
                ull v = fma2_(x2, w10[p], fma2_(z2, w11[p], fma2_(y2, w12[p], b1p[p])));
                h[p] = v;
                sum2 = (p == 0) ? v : add2_(sum2, v);
                sq2  = (p == 0) ? mul2_(v, v) : fma2_(v, v, sq2);
            }
            float slo, shi; upk2(sum2, slo, shi);
            const float mu = (slo + shi) * (1.0f / HID);
            float qlo, qhi; upk2(sq2, qlo, qhi);
            const float m2 = (qlo + qhi) * (1.0f / HID);
            const float var = fmaf(-mu, mu, m2);         // E[h^2] - mu^2
            const float rs = rsq_(var + 1e-5f);
            const ull rs2    = pk2(rs, rs);
            const ull nmurs2 = pk2(-mu * rs, -mu * rs);

            // hn = h*(rs*g) + (beta - mu*rs*g); gelu via rational erf (no div)
            ull acc = 0ULL;
            #pragma unroll
            for (int p = 0; p < NPAIR; p++) {
                const ull rg  = mul2_(rs2, gp[p]);
                const ull off = fma2_(nmurs2, gp[p], bep[p]);
                const ull hn  = fma2_(h[p], rg, off);
                const ull s   = mul2_(hn, hn);
                ull pn = fma2_(s, A13, A11);
                pn = fma2_(s, pn, A9);
                pn = fma2_(s, pn, A7);
                pn = fma2_(s, pn, A5);
                pn = fma2_(s, pn, A3);
                pn = fma2_(s, pn, A1);
                pn = mul2_(pn, hn);            // hn * P'(hn^2)
                ull q = fma2_(s, Bq8, Bq6);
                q = fma2_(s, q, Bq4);
                q = fma2_(s, q, Bq2);
                q = fma2_(s, q, Bq0);          // Q' < 0 for all s >= 0
                float q0, q1; upk2(q, q0, q1);
                const ull rq = pk2(rcp_(q0), rcp_(q1));
                const ull erf2 = mul2_(pn, rq);
                const ull tw = mul2_(hn, w2p[p]);        // hn * (w2/2)
                acc = fma2_(tw, erf2, add2_(acc, tw));   // += hn*w2h*(1+erf)
            }
            float alo, ahi; upk2(acc, alo, ahi);
            const float out = (alo + ahi + b2s) * yv;

            // one packed shared atomic: count + biased fixed-point sum
            const ull pkd = (ull)(__float2ll_rn(out * SUM_SCALE_F) + (long long)ADD_BIAS);
            atomicAdd(&s_acc[idx], pkd);
        }
    }
    __syncthreads();

    // Flush per-CTA partials as integer global atomics (deterministic)
    for (int i = tid; i < ZDIM; i += TPB) {
        const ull v = s_acc[i];
        if (v != 0ULL) {
            const unsigned int cnt = (unsigned int)(v >> CNT_SHIFT);
            const long long raw = (long long)(v & MASK46) - ((long long)cnt << 28);
            atomicAdd(&g_sum_fx[b * ZDIM + i], (ull)raw);
            atomicAdd(&g_cnt[b * ZDIM + i], cnt);
        }
    }

    // ---- last-CTA finalize: means, output, reset scratch ----
    __threadfence();
    if (tid == 0) s_ticket = atomicAdd(&g_done, 1u);
    __syncthreads();
    if (s_ticket == NBLOCKS - 1) {
        __threadfence();
        for (int i = tid; i < BB * ZDIM; i += TPB) {
            const long long sfx = (long long)g_sum_fx[i];
            const unsigned int c = g_cnt[i];
            const double sum = (double)sfx * INV_SCALE;
            OUT[i] = (float)(sum / (double)((c > 0u) ? c : 1u));
            g_sum_fx[i] = 0ULL;
            g_cnt[i] = 0u;
        }
        __syncthreads();
        if (tid == 0) g_done = 0u;
    }
}

extern "C" void kernel_launch(void* const* d_in, const int* in_sizes, int n_in,
                              void* d_out, int out_size) {
    const float* X  = (const float*)d_in[0];
    const float* Y  = (const float*)d_in[1];
    const float* Zb = (const float*)d_in[2];
    const float* W1 = (const float*)d_in[3];
    const float* B1 = (const float*)d_in[4];
    const float* G  = (const float*)d_in[5];
    const float* Be = (const float*)d_in[6];
    const float* W2 = (const float*)d_in[7];
    const float* B2 = (const float*)d_in[8];
    float* out = (float*)d_out;

    dim3 grid(CTAS_PER_B, BB);
    fik_main_kernel<<<grid, TPB>>>(X, Y, Zb, W1, B1, G, Be, W2, B2, out);
}

// round 5
// speedup vs baseline: 1.5340x; 1.1687x over previous
#include <cuda_runtime.h>
#include <math.h>

// Problem constants (fixed by the dataset)
#define BB 8
#define NPB 1048576
#define ZDIM 1024
#define HID 16
#define NPAIR 8
#define TPB 256
#define VEC 4
#define GRIDX 444                              // 148 SMs x 3 CTAs: one balanced wave
#define TILE_ELEMS (TPB * VEC)                 // 1024
#define TILES_TOTAL ((BB * NPB) / TILE_ELEMS)  // 8192
#define TILES_PER_B (NPB / TILE_ELEMS)         // 1024
#define Q0 (TILES_TOTAL / GRIDX)               // 18
#define R0 (TILES_TOTAL % GRIDX)               // 200

// fixed-point packing: addend = (1<<46) + (1<<28) + round(out * 2^21), |out| < 128
// bits [0,46): biased sum (2^-21 units), bits [46,64): count (< 2^18, max ~19456/CTA)
#define SUM_SCALE_F 2097152.0f
#define INV_SCALE   (1.0 / 2097152.0)
#define CNT_SHIFT   46
#define ADD_BIAS    ((1ULL << CNT_SHIFT) | (1ULL << 28))
#define MASK46      ((1ULL << CNT_SHIFT) - 1ULL)

typedef unsigned long long ull;

// ---------- packed f32x2 helpers ----------
__device__ __forceinline__ ull pk2(float lo, float hi) {
    ull r;
    asm("mov.b64 %0, {%1, %2};" : "=l"(r) : "r"(__float_as_uint(lo)), "r"(__float_as_uint(hi)));
    return r;
}
__device__ __forceinline__ void upk2(ull p, float& lo, float& hi) {
    unsigned int a, b;
    asm("mov.b64 {%0, %1}, %2;" : "=r"(a), "=r"(b) : "l"(p));
    lo = __uint_as_float(a); hi = __uint_as_float(b);
}
__device__ __forceinline__ ull fma2_(ull a, ull b, ull c) {
    ull d; asm("fma.rn.f32x2 %0, %1, %2, %3;" : "=l"(d) : "l"(a), "l"(b), "l"(c)); return d;
}
__device__ __forceinline__ ull mul2_(ull a, ull b) {
    ull d; asm("mul.rn.f32x2 %0, %1, %2;" : "=l"(d) : "l"(a), "l"(b)); return d;
}
__device__ __forceinline__ ull add2_(ull a, ull b) {
    ull d; asm("add.rn.f32x2 %0, %1, %2;" : "=l"(d) : "l"(a), "l"(b)); return d;
}
__device__ __forceinline__ float rcp_(float x) {
    float r; asm("rcp.approx.ftz.f32 %0, %1;" : "=f"(r) : "f"(x)); return r;
}
__device__ __forceinline__ float rsq_(float x) {
    float r; asm("rsqrt.approx.ftz.f32 %0, %1;" : "=f"(r) : "f"(x)); return r;
}

// erf-rational constants (1/sqrt2 folded in): erf(hn/sqrt2) = hn*P(hn^2)/Q(hn^2)
struct EC { ull A13, A11, A9, A7, A5, A3, A1, B8, B6, B4, B2, B0; };

__device__ __forceinline__ ull gelu_pair(ull hn, ull w2q, const EC& C) {
    const ull s = mul2_(hn, hn);
    ull pn = fma2_(s, C.A13, C.A11);
    pn = fma2_(s, pn, C.A9);
    pn = fma2_(s, pn, C.A7);
    pn = fma2_(s, pn, C.A5);
    pn = fma2_(s, pn, C.A3);
    pn = fma2_(s, pn, C.A1);
    pn = mul2_(pn, hn);                 // hn * P(hn^2)
    ull q = fma2_(s, C.B8, C.B6);
    q = fma2_(s, q, C.B4);
    q = fma2_(s, q, C.B2);
    q = fma2_(s, q, C.B0);              // Q < 0 for all s >= 0 (no pole)
    float q0, q1; upk2(q, q0, q1);
    const ull rq = pk2(rcp_(q0), rcp_(q1));
    const ull erf2 = mul2_(pn, rq);
    const ull tw = mul2_(hn, w2q);      // hn * (w2/2)
    return fma2_(tw, erf2, tw);         // hn*(w2/2)*(1+erf)
}

// Global scratch (zero at module load; last CTA re-zeros for graph replays).
__device__ ull          g_sum_fx[BB * ZDIM];
__device__ unsigned int g_cnt[BB * ZDIM];
__device__ unsigned int g_done;

__device__ __forceinline__ void flush_acc(ull* s_acc, int b, int tid) {
    for (int i = tid; i < ZDIM; i += TPB) {
        const ull v = s_acc[i];
        if (v != 0ULL) {
            const unsigned int cnt = (unsigned int)(v >> CNT_SHIFT);
            const long long raw = (long long)(v & MASK46) - ((long long)cnt << 28);
            atomicAdd(&g_sum_fx[b * ZDIM + i], (ull)raw);
            atomicAdd(&g_cnt[b * ZDIM + i], cnt);
            s_acc[i] = 0ULL;
        }
    }
}

__global__ __launch_bounds__(TPB, 3) void fik_main_kernel(
    const float* __restrict__ X,   // (B, N)
    const float* __restrict__ Y,   // (B, N, 1)
    const float* __restrict__ Zb,  // (Z,)
    const float* __restrict__ W1,  // (3, HID)
    const float* __restrict__ B1,  // (HID,)
    const float* __restrict__ G,   // gamma
    const float* __restrict__ Be,  // beta
    const float* __restrict__ W2,  // (HID, 1)
    const float* __restrict__ B2,  // (1,)
    float* __restrict__ OUT)       // (B, 1, Z) flat B*Z
{
    __shared__ __align__(8) float s_z[ZDIM];
    __shared__ __align__(16) ull s_acc[ZDIM];
    __shared__ __align__(16) float4 s_wA[NPAIR];   // {w10_0,w10_1,w11_0,w11_1}
    __shared__ __align__(16) float4 s_wB[NPAIR];   // {w12_0,w12_1,b1_0,b1_1}
    __shared__ __align__(16) float4 s_gbe[NPAIR];  // {g0,g1,be0,be1}
    __shared__ __align__(8) float s_w2h[HID];
    __shared__ float s_S[5];                       // S10,S11,S12,Sb,b2
    __shared__ int s_fast;
    __shared__ unsigned int s_ticket;

    const int tid = threadIdx.x;

    for (int i = tid; i < ZDIM; i += TPB) {
        s_z[i] = Zb[i];
        s_acc[i] = 0ULL;
    }
    if (tid < NPAIR) {
        const int j = 2 * tid;
        s_wA[tid]  = make_float4(W1[j], W1[j + 1], W1[HID + j], W1[HID + j + 1]);
        s_wB[tid]  = make_float4(W1[2 * HID + j], W1[2 * HID + j + 1], B1[j], B1[j + 1]);
        s_gbe[tid] = make_float4(G[j], G[j + 1], Be[j], Be[j + 1]);
        s_w2h[j]     = W2[j] * 0.5f;
        s_w2h[j + 1] = W2[j + 1] * 0.5f;
    }
    if (tid == 0) {
        float a = 0.f, b = 0.f, c = 0.f, d = 0.f;
        int f = 1;
        for (int j = 0; j < HID; j++) {
            a += W1[j]; b += W1[HID + j]; c += W1[2 * HID + j]; d += B1[j];
            f &= (G[j] == 1.0f) & (Be[j] == 0.0f);
        }
        s_S[0] = a * (1.0f / HID); s_S[1] = b * (1.0f / HID);
        s_S[2] = c * (1.0f / HID); s_S[3] = d * (1.0f / HID);
        s_S[4] = B2[0];
        s_fast = f;
    }
    __syncthreads();

    const ulonglong2* wA  = (const ulonglong2*)s_wA;
    const ulonglong2* wB  = (const ulonglong2*)s_wB;
    const ulonglong2* gbe = (const ulonglong2*)s_gbe;
    const ull* w2p = (const ull*)s_w2h;

    const float z0  = s_z[0];
    const float dz  = s_z[1] - s_z[0];
    const float dzh = dz * 0.5f;
    const float inv_dz = 1.0f / dz;
    const float S10 = s_S[0], S11 = s_S[1], S12 = s_S[2], S1b = s_S[3], b2s = s_S[4];
    const int fastf = s_fast;

    EC C;
    C.A13 = pk2(-3.01199e-12f, -3.01199e-12f);
    C.A11 = pk2( 6.12251e-10f,  6.12251e-10f);
    C.A9  = pk2(-9.28533e-08f, -9.28533e-08f);
    C.A7  = pk2(-5.03151e-06f, -5.03151e-06f);
    C.A5  = pk2(-1.299293e-04f, -1.299293e-04f);
    C.A3  = pk2(-1.044617e-03f, -1.044617e-03f);
    C.A1  = pk2(-1.1381612e-02f, -1.1381612e-02f);
    C.B8  = pk2(-9.10379490e-07f, -9.10379490e-07f);
    C.B6  = pk2(-2.66717569e-05f, -2.66717569e-05f);
    C.B4  = pk2(-4.20706744e-04f, -4.20706744e-04f);
    C.B2  = pk2(-3.68666458e-03f, -3.68666458e-03f);
    C.B0  = pk2(-1.42647391e-02f, -1.42647391e-02f);

    // contiguous tile range for this CTA (persistent, one balanced wave)
    const int c = blockIdx.x;
    const int start = c * Q0 + min(c, R0);
    const int cnt = Q0 + (c < R0 ? 1 : 0);
    int cur_b = start / TILES_PER_B;

    const float4* X4 = (const float4*)X;
    const float4* Y4 = (const float4*)Y;

    float4 xv4 = X4[start * TPB + tid];
    float4 yv4 = Y4[start * TPB + tid];

    #pragma unroll 1
    for (int k = 0; k < cnt; k++) {
        const int t = start + k;
        const int b = t / TILES_PER_B;
        if (b != cur_b) {
            __syncthreads();
            flush_acc(s_acc, cur_b, tid);
            __syncthreads();
            cur_b = b;
        }
        const float4 xcur = xv4, ycur = yv4;
        if (k + 1 < cnt) {                       // prefetch next tile
            xv4 = X4[(t + 1) * TPB + tid];
            yv4 = Y4[(t + 1) * TPB + tid];
        }

        #pragma unroll
        for (int e = 0; e < VEC; e++) {
            const float xv = (e == 0) ? xcur.x : (e == 1) ? xcur.y : (e == 2) ? xcur.z : xcur.w;
            const float yv = (e == 0) ? ycur.x : (e == 1) ? ycur.y : (e == 2) ? ycur.z : ycur.w;

            float tt = ((xv - z0) - dzh) * inv_dz;
            int idx = (int)ceilf(tt);
            idx = min(max(idx, 0), ZDIM - 1);
            const float zg = s_z[idx];

            const ull x2 = pk2(xv, xv);
            const ull z2 = pk2(zg, zg);
            const ull y2 = pk2(yv, yv);

            // h = [x, zg, y] @ W1 + b1;  sum(h^2) alongside
            ull hv[NPAIR];
            ull sq;
            #pragma unroll
            for (int p = 0; p < NPAIR; p++) {
                const ulonglong2 a = wA[p];
                const ulonglong2 bq = wB[p];
                const ull v = fma2_(x2, a.x, fma2_(z2, a.y, fma2_(y2, bq.x, bq.y)));
                hv[p] = v;
                sq = (p == 0) ? mul2_(v, v) : fma2_(v, v, sq);
            }
            // mu is linear in (x, zg, y): 3 scalar FMAs with row-means
            const float mu = fmaf(xv, S10, fmaf(zg, S11, fmaf(yv, S12, S1b)));
            float qlo, qhi; upk2(sq, qlo, qhi);
            const float m2 = (qlo + qhi) * (1.0f / HID);
            const float var = fmaf(-mu, mu, m2);
            const float rs = rsq_(var + 1e-5f);
            const float nm = -mu * rs;
            const ull rs2 = pk2(rs, rs);
            const ull nm2 = pk2(nm, nm);

            ull acc = 0ULL;
            if (fastf) {          // gamma == 1, beta == 0 (verified at runtime)
                #pragma unroll
                for (int p = 0; p < NPAIR; p++) {
                    const ull hn = fma2_(hv[p], rs2, nm2);
                    acc = add2_(acc, gelu_pair(hn, w2p[p], C));
                }
            } else {
                #pragma unroll
                for (int p = 0; p < NPAIR; p++) {
                    const ulonglong2 gb = gbe[p];
                    const ull hn = fma2_(fma2_(hv[p], rs2, nm2), gb.x, gb.y);
                    acc = add2_(acc, gelu_pair(hn, w2p[p], C));
                }
            }
            float alo, ahi; upk2(acc, alo, ahi);
            const float outv = (alo + ahi + b2s) * yv;

            const ull pkd = (ull)(__float2ll_rn(outv * SUM_SCALE_F) + (long long)ADD_BIAS);
            atomicAdd(&s_acc[idx], pkd);
        }
    }
    __syncthreads();
    flush_acc(s_acc, cur_b, tid);

    // ---- last-CTA finalize: means, output, reset scratch ----
    __threadfence();
    if (tid == 0) s_ticket = atomicAdd(&g_done, 1u);
    __syncthreads();
    if (s_ticket == GRIDX - 1) {
        __threadfence();
        for (int i = tid; i < BB * ZDIM; i += TPB) {
            const long long sfx = (long long)g_sum_fx[i];
            const unsigned int cc = g_cnt[i];
            const double sum = (double)sfx * INV_SCALE;
            OUT[i] = (float)(sum / (double)((cc > 0u) ? cc : 1u));
            g_sum_fx[i] = 0ULL;
            g_cnt[i] = 0u;
        }
        __syncthreads();
        if (tid == 0) g_done = 0u;
    }
}

extern "C" void kernel_launch(void* const* d_in, const int* in_sizes, int n_in,
                              void* d_out, int out_size) {
    const float* X  = (const float*)d_in[0];
    const float* Y  = (const float*)d_in[1];
    const float* Zb = (const float*)d_in[2];
    const float* W1 = (const float*)d_in[3];
    const float* B1 = (const float*)d_in[4];
    const float* G  = (const float*)d_in[5];
    const float* Be = (const float*)d_in[6];
    const float* W2 = (const float*)d_in[7];
    const float* B2 = (const float*)d_in[8];
    float* out = (float*)d_out;

    fik_main_kernel<<<GRIDX, TPB>>>(X, Y, Zb, W1, B1, G, Be, W2, B2, out);
}

// round 6
// speedup vs baseline: 1.5821x; 1.0314x over previous
#include <cuda_runtime.h>
#include <math.h>

// Problem constants (fixed by the dataset)
#define BB 8
#define NPB 1048576
#define ZDIM 1024
#define HID 16
#define NPAIR 8
#define TPB 256
#define VEC 4
#define GRIDX 444                              // 148 SMs x 3 CTAs... now 4/SM; still one wave
#define TILE_ELEMS (TPB * VEC)                 // 1024
#define TILES_TOTAL ((BB * NPB) / TILE_ELEMS)  // 8192
#define TILES_PER_B (NPB / TILE_ELEMS)         // 1024
#define Q0 (TILES_TOTAL / GRIDX)               // 18
#define R0 (TILES_TOTAL % GRIDX)               // 200

// fixed-point packing: addend = (1<<46) + (1<<28) + round(out * 2^21), |out| < 128
// Sums of addends keep: bits [46,64) = count, bits [0,46) = count*2^28 + sum_fx.
// Global worst case per (b,bucket): cnt ~1.4K -> low field < 2^40 << 2^46. Safe.
#define SUM_SCALE_F 2097152.0f
#define INV_SCALE   (1.0 / 2097152.0)
#define CNT_SHIFT   46
#define ADD_BIAS    ((1ULL << CNT_SHIFT) | (1ULL << 28))
#define MASK46      ((1ULL << CNT_SHIFT) - 1ULL)

typedef unsigned long long ull;

// ---------- packed f32x2 helpers ----------
__device__ __forceinline__ ull pk2(float lo, float hi) {
    ull r;
    asm("mov.b64 %0, {%1, %2};" : "=l"(r) : "r"(__float_as_uint(lo)), "r"(__float_as_uint(hi)));
    return r;
}
__device__ __forceinline__ void upk2(ull p, float& lo, float& hi) {
    unsigned int a, b;
    asm("mov.b64 {%0, %1}, %2;" : "=r"(a), "=r"(b) : "l"(p));
    lo = __uint_as_float(a); hi = __uint_as_float(b);
}
__device__ __forceinline__ ull fma2_(ull a, ull b, ull c) {
    ull d; asm("fma.rn.f32x2 %0, %1, %2, %3;" : "=l"(d) : "l"(a), "l"(b), "l"(c)); return d;
}
__device__ __forceinline__ ull mul2_(ull a, ull b) {
    ull d; asm("mul.rn.f32x2 %0, %1, %2;" : "=l"(d) : "l"(a), "l"(b)); return d;
}
__device__ __forceinline__ ull add2_(ull a, ull b) {
    ull d; asm("add.rn.f32x2 %0, %1, %2;" : "=l"(d) : "l"(a), "l"(b)); return d;
}
__device__ __forceinline__ float rcp_(float x) {
    float r; asm("rcp.approx.ftz.f32 %0, %1;" : "=f"(r) : "f"(x)); return r;
}
__device__ __forceinline__ float rsq_(float x) {
    float r; asm("rsqrt.approx.ftz.f32 %0, %1;" : "=f"(r) : "f"(x)); return r;
}

// erf-rational constants (1/sqrt2 folded): erf(hn/sqrt2) = hn*P(hn^2)/Q(hn^2)
struct EC { ull A13, A11, A9, A7, A5, A3, A1, B8, B6, B4, B2, B0; };

__device__ __forceinline__ ull gelu_pair(ull hn, ull w2q, const EC& C) {
    const ull s = mul2_(hn, hn);
    ull pn = fma2_(s, C.A13, C.A11);
    pn = fma2_(s, pn, C.A9);
    pn = fma2_(s, pn, C.A7);
    pn = fma2_(s, pn, C.A5);
    pn = fma2_(s, pn, C.A3);
    pn = fma2_(s, pn, C.A1);
    pn = mul2_(pn, hn);                 // hn * P(hn^2)
    ull q = fma2_(s, C.B8, C.B6);
    q = fma2_(s, q, C.B4);
    q = fma2_(s, q, C.B2);
    q = fma2_(s, q, C.B0);              // Q < 0 for all s >= 0 (no pole)
    float q0, q1; upk2(q, q0, q1);
    const ull rq = pk2(rcp_(q0), rcp_(q1));
    const ull erf2 = mul2_(pn, rq);
    const ull tw = mul2_(hn, w2q);      // hn * (w2/2)
    return fma2_(tw, erf2, tw);         // hn*(w2/2)*(1+erf)
}

// Global scratch: one packed accumulator per (b, bucket). Zero at load;
// last CTA re-zeros for graph replays.
__device__ ull          g_acc64[BB * ZDIM];
__device__ unsigned int g_done;

__device__ __forceinline__ void flush_acc(ull* s_acc, int b, int tid) {
    for (int i = tid; i < ZDIM; i += TPB) {
        const ull v = s_acc[i];
        if (v != 0ULL) {
            atomicAdd(&g_acc64[b * ZDIM + i], v);   // packed add is homomorphic
            s_acc[i] = 0ULL;
        }
    }
}

__global__ __launch_bounds__(TPB, 4) void fik_main_kernel(
    const float* __restrict__ X,   // (B, N)
    const float* __restrict__ Y,   // (B, N, 1)
    const float* __restrict__ Zb,  // (Z,)
    const float* __restrict__ W1,  // (3, HID)
    const float* __restrict__ B1,  // (HID,)
    const float* __restrict__ G,   // gamma
    const float* __restrict__ Be,  // beta
    const float* __restrict__ W2,  // (HID, 1)
    const float* __restrict__ B2,  // (1,)
    float* __restrict__ OUT)       // (B, 1, Z) flat B*Z
{
    __shared__ __align__(8) float s_z[ZDIM];
    __shared__ __align__(16) ull s_acc[ZDIM];
    __shared__ __align__(16) float4 s_wA[NPAIR];   // {w10_0,w10_1,w11_0,w11_1}
    __shared__ __align__(16) float4 s_wB[NPAIR];   // {w12_0,w12_1,b1_0,b1_1}
    __shared__ __align__(16) float4 s_gbe[NPAIR];  // {g0,g1,be0,be1}
    __shared__ __align__(8) float s_w2h[HID];
    __shared__ float s_S[5];                       // S10,S11,S12,Sb,b2
    __shared__ int s_fast;
    __shared__ unsigned int s_ticket;

    const int tid = threadIdx.x;

    for (int i = tid; i < ZDIM; i += TPB) {
        s_z[i] = Zb[i];
        s_acc[i] = 0ULL;
    }
    if (tid < NPAIR) {
        const int j = 2 * tid;
        s_wA[tid]  = make_float4(W1[j], W1[j + 1], W1[HID + j], W1[HID + j + 1]);
        s_wB[tid]  = make_float4(W1[2 * HID + j], W1[2 * HID + j + 1], B1[j], B1[j + 1]);
        s_gbe[tid] = make_float4(G[j], G[j + 1], Be[j], Be[j + 1]);
        s_w2h[j]     = W2[j] * 0.5f;
        s_w2h[j + 1] = W2[j + 1] * 0.5f;
    }
    if (tid == 0) {
        float a = 0.f, b = 0.f, c = 0.f, d = 0.f;
        int f = 1;
        for (int j = 0; j < HID; j++) {
            a += W1[j]; b += W1[HID + j]; c += W1[2 * HID + j]; d += B1[j];
            f &= (G[j] == 1.0f) & (Be[j] == 0.0f);
        }
        s_S[0] = a * (1.0f / HID); s_S[1] = b * (1.0f / HID);
        s_S[2] = c * (1.0f / HID); s_S[3] = d * (1.0f / HID);
        s_S[4] = B2[0];
        s_fast = f;
    }
    __syncthreads();

    const ulonglong2* wA  = (const ulonglong2*)s_wA;
    const ulonglong2* wB  = (const ulonglong2*)s_wB;
    const ulonglong2* gbe = (const ulonglong2*)s_gbe;
    const ull* w2p = (const ull*)s_w2h;

    const float z0  = s_z[0];
    const float dz  = s_z[1] - s_z[0];
    const float inv_dz = 1.0f / dz;
    const float c1 = (z0 + dz * 0.5f) * inv_dz;    // t = x*inv_dz - c1
    const float S10 = s_S[0], S11 = s_S[1], S12 = s_S[2], S1b = s_S[3], b2s = s_S[4];
    const int fastf = s_fast;

    EC C;
    C.A13 = pk2(-3.01199e-12f, -3.01199e-12f);
    C.A11 = pk2( 6.12251e-10f,  6.12251e-10f);
    C.A9  = pk2(-9.28533e-08f, -9.28533e-08f);
    C.A7  = pk2(-5.03151e-06f, -5.03151e-06f);
    C.A5  = pk2(-1.299293e-04f, -1.299293e-04f);
    C.A3  = pk2(-1.044617e-03f, -1.044617e-03f);
    C.A1  = pk2(-1.1381612e-02f, -1.1381612e-02f);
    C.B8  = pk2(-9.10379490e-07f, -9.10379490e-07f);
    C.B6  = pk2(-2.66717569e-05f, -2.66717569e-05f);
    C.B4  = pk2(-4.20706744e-04f, -4.20706744e-04f);
    C.B2  = pk2(-3.68666458e-03f, -3.68666458e-03f);
    C.B0  = pk2(-1.42647391e-02f, -1.42647391e-02f);

    // contiguous tile range for this CTA (persistent, balanced)
    const int c = blockIdx.x;
    const int start = c * Q0 + min(c, R0);
    const int cnt = Q0 + (c < R0 ? 1 : 0);
    int cur_b = start / TILES_PER_B;

    const float4* X4 = (const float4*)X;
    const float4* Y4 = (const float4*)Y;

    #pragma unroll 1
    for (int k = 0; k < cnt; k++) {
        const int t = start + k;
        const int b = t / TILES_PER_B;
        if (b != cur_b) {
            __syncthreads();
            flush_acc(s_acc, cur_b, tid);
            __syncthreads();
            cur_b = b;
        }
        const float4 xcur = X4[t * TPB + tid];
        const float4 ycur = Y4[t * TPB + tid];
        ull* __restrict__ gacc_b = g_acc64 + b * ZDIM;

        #pragma unroll
        for (int e = 0; e < VEC; e++) {
            const float xv = (e == 0) ? xcur.x : (e == 1) ? xcur.y : (e == 2) ? xcur.z : xcur.w;
            const float yv = (e == 0) ? ycur.x : (e == 1) ? ycur.y : (e == 2) ? ycur.z : ycur.w;

            int idx = __float2int_ru(fmaf(xv, inv_dz, -c1));   // ceil((x-z0-dz/2)/dz)
            idx = min(max(idx, 0), ZDIM - 1);
            const float zg = s_z[idx];

            const ull x2 = pk2(xv, xv);
            const ull z2 = pk2(zg, zg);
            const ull y2 = pk2(yv, yv);

            // h = [x, zg, y] @ W1 + b1;  sum(h^2) alongside
            ull hv[NPAIR];
            ull sq;
            #pragma unroll
            for (int p = 0; p < NPAIR; p++) {
                const ulonglong2 a = wA[p];
                const ulonglong2 bq = wB[p];
                const ull v = fma2_(x2, a.x, fma2_(z2, a.y, fma2_(y2, bq.x, bq.y)));
                hv[p] = v;
                sq = (p == 0) ? mul2_(v, v) : fma2_(v, v, sq);
            }
            // mu is linear in (x, zg, y)
            const float mu = fmaf(xv, S10, fmaf(zg, S11, fmaf(yv, S12, S1b)));
            float qlo, qhi; upk2(sq, qlo, qhi);
            const float m2 = (qlo + qhi) * (1.0f / HID);
            const float var = fmaf(-mu, mu, m2);
            const float rs = rsq_(var + 1e-5f);
            const float nm = -mu * rs;
            const ull rs2 = pk2(rs, rs);
            const ull nm2 = pk2(nm, nm);

            ull acc = 0ULL;
            if (fastf) {          // gamma == 1, beta == 0 (runtime-verified)
                #pragma unroll
                for (int p = 0; p < NPAIR; p++) {
                    const ull hn = fma2_(hv[p], rs2, nm2);
                    acc = add2_(acc, gelu_pair(hn, w2p[p], C));
                }
            } else {
                #pragma unroll
                for (int p = 0; p < NPAIR; p++) {
                    const ulonglong2 gb = gbe[p];
                    const ull hn = fma2_(fma2_(hv[p], rs2, nm2), gb.x, gb.y);
                    acc = add2_(acc, gelu_pair(hn, w2p[p], C));
                }
            }
            float alo, ahi; upk2(acc, alo, ahi);
            const float outv = (alo + ahi + b2s) * yv;

            const ull pkd = (ull)(__float2ll_rn(outv * SUM_SCALE_F) + (long long)ADD_BIAS);
            if (e & 1) {
                atomicAdd(&gacc_b[idx], pkd);    // L2 RED path (half the elements)
            } else {
                atomicAdd(&s_acc[idx], pkd);     // shared ATOMS path
            }
        }
    }
    __syncthreads();
    flush_acc(s_acc, cur_b, tid);

    // ---- last-CTA finalize: means, output, reset scratch ----
    __threadfence();
    if (tid == 0) s_ticket = atomicAdd(&g_done, 1u);
    __syncthreads();
    if (s_ticket == GRIDX - 1) {
        __threadfence();
        for (int i = tid; i < BB * ZDIM; i += TPB) {
            const ull v = g_acc64[i];
            const unsigned int cc = (unsigned int)(v >> CNT_SHIFT);
            const long long sfx = (long long)(v & MASK46) - ((long long)cc << 28);
            const double sum = (double)sfx * INV_SCALE;
            OUT[i] = (float)(sum / (double)((cc > 0u) ? cc : 1u));
            g_acc64[i] = 0ULL;
        }
        __syncthreads();
        if (tid == 0) g_done = 0u;
    }
}

extern "C" void kernel_launch(void* const* d_in, const int* in_sizes, int n_in,
                              void* d_out, int out_size) {
    const float* X  = (const float*)d_in[0];
    const float* Y  = (const float*)d_in[1];
    const float* Zb = (const float*)d_in[2];
    const float* W1 = (const float*)d_in[3];
    const float* B1 = (const float*)d_in[4];
    const float* G  = (const float*)d_in[5];
    const float* Be = (const float*)d_in[6];
    const float* W2 = (const float*)d_in[7];
    const float* B2 = (const float*)d_in[8];
    float* out = (float*)d_out;

    fik_main_kernel<<<GRIDX, TPB>>>(X, Y, Zb, W1, B1, G, Be, W2, B2, out);
}